// round 10
// baseline (speedup 1.0000x reference)
#include <cuda_runtime.h>

// ---------------- problem constants ----------------
#define C 96                 // feature channels (d = h = 96)
#define NMAX 65536
#define EMAX 1048576

// ---------------- device scratch (no allocations allowed) ----------------
__device__ int   d_is64;
__device__ int   d_deg[NMAX];
__device__ int   d_rowptr[NMAX];       // tile-LOCAL exclusive scan
__device__ int   d_cursor[NMAX];       // tile-LOCAL fill cursor
__device__ int   d_bsum[1024];         // per-tile degree totals
__device__ int   d_boff[1024];         // per-tile global offsets
__device__ int2  d_csr[EMAX];
__device__ float d_dinv[NMAX];
__device__ float d_h1[(size_t)NMAX * C];
__device__ float d_xgcn[(size_t)NMAX * C];
__device__ float d_g[(size_t)NMAX * C];

// grid-barrier state (monotonic generation; survives across graph replays)
__device__ unsigned          d_barcnt = 0;
__device__ volatile unsigned d_bargen = 0;
__device__ unsigned          d_p2done = 0;   // last-block ticket for mid-scan

// ---------------- helpers ----------------
__device__ __forceinline__ float fsigmoid(float x) {
    return 1.0f / (1.0f + __expf(-x));
}
__device__ __forceinline__ float ftanh(float x) {
    return 1.0f - 2.0f / (__expf(2.0f * x) + 1.0f);
}
__device__ __forceinline__ int load_idx(const void* ei, int idx, int is64) {
    if (is64) return (int)((const long long*)ei)[idx];
    return ((const int*)ei)[idx];
}

// Software grid barrier (all blocks co-resident; grid sized via occupancy API).
__device__ __forceinline__ void grid_barrier() {
    __threadfence();
    __syncthreads();
    if (threadIdx.x == 0) {
        unsigned g = d_bargen;
        unsigned t = atomicAdd(&d_barcnt, 1u);
        if (t == gridDim.x - 1) {
            atomicExch(&d_barcnt, 0u);
            __threadfence();
            d_bargen = g + 1;
        } else {
            while (d_bargen == g) __nanosleep(64);
        }
    }
    __syncthreads();
    __threadfence();
}

// ---------------- GEMM phase v5: 4 rows/thread (0.25 LDS-word/FMA) --------
// out[N,96] = A[N,K] @ W[K,96]; K in 96-row segments, one staged in smem.
// Segment 1 accumulates via out += (same thread owns the same elements).
// Warp owns 16 rows x 96 cols: lane (g=lane&7, s=lane>>3) holds acc[4][12]
// for rows (tile*128 + wid*16 + s*4 +{0..3}), cols g*12..+11.
// Per 4-k chunk: 4 LDG.128 (one per row), inner 4x(3 LDS.128 W -> 48 FMA).
template <int MODE>
__device__ __forceinline__ float4 gemm_load_row4(
    const float* __restrict__ Asrc, const float* __restrict__ A2,
    int seg, int row, int k0, bool valid)
{
    if (!valid) return make_float4(0.f, 0.f, 0.f, 0.f);
    float4 v = *(const float4*)(Asrc + (size_t)row * C + k0);
    if (MODE == 2 && seg == 1) {
        float4 gv = *(const float4*)(A2 + (size_t)row * C + k0);
        v.x *= gv.x; v.y *= gv.y; v.z *= gv.z; v.w *= gv.w;
    }
    return v;
}

template <int MODE>
__device__ void gemm_phase(
    const float* __restrict__ A0, const float* __restrict__ A1,
    const float* __restrict__ A2, const float* __restrict__ W,
    float* __restrict__ outp, int N, float* sW)
{
    const int NSEG = (MODE == 0) ? 1 : 2;
    const int tid  = threadIdx.x;
    const int lane = tid & 31;
    const int wid  = tid >> 5;
    const int g    = lane & 7;
    const int s    = lane >> 3;
    const int ntile = (N + 127) / 128;

    for (int seg = 0; seg < NSEG; seg++) {
        __syncthreads();                          // prior users of sW done
        const float* wseg = W + (size_t)seg * C * C;
        for (int i = tid * 4; i < C * C; i += 256 * 4)
            *(float4*)&sW[i] = *(const float4*)&wseg[i];
        __syncthreads();

        const float* Asrc = (seg == 0) ? A0 : A1;

        for (int tile = blockIdx.x; tile < ntile; tile += gridDim.x) {
            const int rbase = tile * 128 + wid * 16 + s * 4;

            float acc[4][12];
            #pragma unroll
            for (int r = 0; r < 4; r++)
                #pragma unroll
                for (int c2 = 0; c2 < 12; c2++) acc[r][c2] = 0.0f;

            const bool v[4] = { rbase < N, rbase + 1 < N,
                                rbase + 2 < N, rbase + 3 < N };

            #pragma unroll 2
            for (int ch = 0; ch < 24; ch++) {     // 4-k chunks
                const int k0 = ch * 4;
                float4 p[4];
                #pragma unroll
                for (int r = 0; r < 4; r++)
                    p[r] = gemm_load_row4<MODE>(Asrc, A2, seg, rbase + r, k0, v[r]);

                const float* wbase = &sW[k0 * C + g * 12];
                #pragma unroll
                for (int kk = 0; kk < 4; kk++) {
                    const float* wr = wbase + kk * C;
                    float4 w0 = *(const float4*)(wr);
                    float4 w1 = *(const float4*)(wr + 4);
                    float4 w2 = *(const float4*)(wr + 8);
                    #pragma unroll
                    for (int r = 0; r < 4; r++) {
                        float av = (kk == 0) ? p[r].x :
                                   (kk == 1) ? p[r].y :
                                   (kk == 2) ? p[r].z : p[r].w;
                        acc[r][0]  += av * w0.x; acc[r][1]  += av * w0.y;
                        acc[r][2]  += av * w0.z; acc[r][3]  += av * w0.w;
                        acc[r][4]  += av * w1.x; acc[r][5]  += av * w1.y;
                        acc[r][6]  += av * w1.z; acc[r][7]  += av * w1.w;
                        acc[r][8]  += av * w2.x; acc[r][9]  += av * w2.y;
                        acc[r][10] += av * w2.z; acc[r][11] += av * w2.w;
                    }
                }
            }

            #pragma unroll
            for (int r = 0; r < 4; r++) {
                if (v[r]) {
                    float* o = outp + (size_t)(rbase + r) * C + g * 12;
                    if (seg == 0) {
                        *(float4*)(o)     = make_float4(acc[r][0], acc[r][1],
                                                        acc[r][2], acc[r][3]);
                        *(float4*)(o + 4) = make_float4(acc[r][4], acc[r][5],
                                                        acc[r][6], acc[r][7]);
                        *(float4*)(o + 8) = make_float4(acc[r][8], acc[r][9],
                                                        acc[r][10], acc[r][11]);
                    } else {
                        float4 o0 = *(float4*)(o);
                        float4 o1 = *(float4*)(o + 4);
                        float4 o2 = *(float4*)(o + 8);
                        *(float4*)(o)     = make_float4(o0.x + acc[r][0], o0.y + acc[r][1],
                                                        o0.z + acc[r][2], o0.w + acc[r][3]);
                        *(float4*)(o + 4) = make_float4(o1.x + acc[r][4], o1.y + acc[r][5],
                                                        o1.z + acc[r][6], o1.w + acc[r][7]);
                        *(float4*)(o + 8) = make_float4(o2.x + acc[r][8], o2.y + acc[r][9],
                                                        o2.z + acc[r][10], o2.w + acc[r][11]);
                    }
                }
            }
        }
    }
}

// ---------------- aggregation phase ----------------
// task = (node, channel-third); lane owns channel third*32+lane.
// Global CSR position = tile-local rowptr + per-tile offset; extent = deg[n].
template <int MODE>
__device__ void agg_phase(
    const float* __restrict__ H, const float* __restrict__ bias,
    const float* __restrict__ G, const float* __restrict__ HP,
    float* __restrict__ outp, int N, int2* sCS)
{
    const int wid  = threadIdx.x >> 5;
    const int lane = threadIdx.x & 31;
    int2* cs = &sCS[wid * 32];
    const int ntask = 3 * N;

    for (int task = blockIdx.x * 8 + wid; task < ntask; task += gridDim.x * 8) {
        const int n     = task / 3;
        const int third = task - n * 3;
        const int c     = third * 32 + lane;

        float dn = d_dinv[n];
        float a  = bias[c] + dn * dn * H[(size_t)n * C + c];

        const int jbeg = d_rowptr[n] + d_boff[n >> 8];
        const int jend = jbeg + d_deg[n];

        for (int base = jbeg; base < jend; base += 32) {
            int cnt = jend - base;
            if (cnt > 32) cnt = 32;
            if (lane < cnt) cs[lane] = d_csr[base + lane];
            __syncwarp();
            int t = 0;
            for (; t + 8 <= cnt; t += 8) {
                float xv[8], wv[8];
                #pragma unroll
                for (int q = 0; q < 8; q++) {
                    int2 e = cs[t + q];
                    wv[q] = __int_as_float(e.y);
                    xv[q] = H[(size_t)e.x * C + c];
                }
                #pragma unroll
                for (int q = 0; q < 8; q++) a += wv[q] * xv[q];
            }
            for (; t < cnt; t++) {
                int2 e = cs[t];
                a += __int_as_float(e.y) * H[(size_t)e.x * C + c];
            }
            __syncwarp();
        }

        const size_t o = (size_t)n * C + c;
        if (MODE == 0) {
            outp[o] = a;
        } else if (MODE == 1) {
            outp[o] = fsigmoid(a);
        } else {
            float u = G[o];
            outp[o] = u * HP[o] + (1.0f - u) * ftanh(a);
        }
    }
}

// ---------------- the megakernel ----------------
__global__ void __launch_bounds__(256, 3) mega_kernel(
    const float* __restrict__ x, const void* __restrict__ ei,
    const float* __restrict__ h_prev,
    const float* __restrict__ Wx,  const float* __restrict__ bx,
    const float* __restrict__ Wuh, const float* __restrict__ buh,
    const float* __restrict__ Wch, const float* __restrict__ bch,
    float* __restrict__ out, int N, int E)
{
    extern __shared__ float sW[];                 // [C*C] floats (36 KB)
    int2* sCS = (int2*)(sW + C * C);              // [8*32] int2 (2 KB)
    int*  sSc = (int*)sCS;                        // scan scratch (aliased)

    const int tid  = threadIdx.x;
    const int NB   = gridDim.x;
    const int gtid = blockIdx.x * 256 + tid;
    const int nthr = NB * 256;
    const int lane = tid & 31;
    const int wid  = tid >> 5;

    // ---- Phase A: zero deg + dtype detect (block 0) + gemm<0> ----
    for (int i = gtid; i < N; i += nthr) d_deg[i] = 0;
    if (blockIdx.x == 0) {
        int lim = 2 * E; if (lim > 8192) lim = 8192;
        int nz = 0;
        const int* e32 = (const int*)ei;
        for (int i = 1 + 2 * tid; i < lim; i += 512) nz |= e32[i];
        #pragma unroll
        for (int off = 16; off > 0; off >>= 1)
            nz |= __shfl_xor_sync(0xffffffffu, nz, off);
        if (lane == 0) sSc[wid] = nz;
        __syncthreads();
        if (tid == 0) {
            int r = 0;
            #pragma unroll
            for (int w = 0; w < 8; w++) r |= sSc[w];
            d_is64 = (r == 0) ? 1 : 0;
        }
        __syncthreads();
    }
    gemm_phase<0>(x, nullptr, nullptr, Wx, d_h1, N, sW);
    grid_barrier();                                            // B1

    const int is64 = d_is64;

    // ---- Phase B: degree histogram ----
    for (int e = gtid; e < E; e += nthr) {
        int d = load_idx(ei, E + e, is64);
        if ((unsigned)d < (unsigned)N) atomicAdd(&d_deg[d], 1);
    }
    grid_barrier();                                            // B2

    // ---- Phase C: per-tile local scan + dinv; LAST block does mid-scan ----
    const int ntiles = (N + 255) / 256;
    for (int tile = blockIdx.x; tile < ntiles; tile += NB) {
        int i = tile * 256 + tid;
        int v = (i < N) ? d_deg[i] : 0;
        if (i < N) d_dinv[i] = rsqrtf((float)v + 1.0f);
        int xv = v;
        #pragma unroll
        for (int off = 1; off < 32; off <<= 1) {
            int y = __shfl_up_sync(0xffffffffu, xv, off);
            if (lane >= off) xv += y;
        }
        if (lane == 31) sSc[wid] = xv;
        __syncthreads();
        if (wid == 0 && lane < 8) {
            int s2 = sSc[lane];
            #pragma unroll
            for (int off = 1; off < 8; off <<= 1) {
                int y = __shfl_up_sync(0xffu, s2, off);
                if (lane >= off) s2 += y;
            }
            sSc[lane] = s2;
        }
        __syncthreads();
        int incl = xv + ((wid > 0) ? sSc[wid - 1] : 0);
        if (i < N) {
            int excl = incl - v;
            d_rowptr[i] = excl;                    // tile-local
            d_cursor[i] = excl;
        }
        if (tid == 255) d_bsum[tile] = incl;
        __syncthreads();
    }
    // last-block ticket -> mid-scan of tile totals
    {
        __shared__ int amLast;
        __threadfence();
        __syncthreads();
        if (tid == 0) {
            unsigned t = atomicAdd(&d_p2done, 1u);
            amLast = (t == (unsigned)(NB - 1));
            if (amLast) d_p2done = 0;
        }
        __syncthreads();
        if (amLast) {
            __threadfence();                       // acquire bsum writes
            int v = (tid < ntiles) ? d_bsum[tid] : 0;
            int xv = v;
            #pragma unroll
            for (int off = 1; off < 32; off <<= 1) {
                int y = __shfl_up_sync(0xffffffffu, xv, off);
                if (lane >= off) xv += y;
            }
            if (lane == 31) sSc[wid] = xv;
            __syncthreads();
            if (wid == 0 && lane < 8) {
                int s2 = sSc[lane];
                #pragma unroll
                for (int off = 1; off < 8; off <<= 1) {
                    int y = __shfl_up_sync(0xffu, s2, off);
                    if (lane >= off) s2 += y;
                }
                sSc[lane] = s2;
            }
            __syncthreads();
            int incl = xv + ((wid > 0) ? sSc[wid - 1] : 0);
            if (tid < ntiles) d_boff[tid] = incl - v;
        }
    }
    grid_barrier();                                            // B3

    // ---- Phase D: CSR fill (global pos = local cursor + tile offset) ----
    for (int e = gtid; e < E; e += nthr) {
        int s = load_idx(ei, e, is64);
        int d = load_idx(ei, E + e, is64);
        if ((unsigned)s < (unsigned)N && (unsigned)d < (unsigned)N) {
            int p = atomicAdd(&d_cursor[d], 1) + d_boff[d >> 8];
            d_csr[p] = make_int2(s, __float_as_int(d_dinv[s] * d_dinv[d]));
        }
    }
    grid_barrier();                                            // B4

    // ---- Phases E..I: agg0, gemm1, agg1, gemm2, agg2 ----
    agg_phase<0>(d_h1, bx, nullptr, nullptr, d_xgcn, N, sCS);
    grid_barrier();                                            // B5

    gemm_phase<1>(d_xgcn, h_prev, nullptr, Wuh, d_h1, N, sW);
    grid_barrier();                                            // B6

    agg_phase<1>(d_h1, buh, nullptr, nullptr, d_g, N, sCS);
    grid_barrier();                                            // B7

    gemm_phase<2>(d_xgcn, h_prev, d_g, Wch, d_h1, N, sW);
    grid_barrier();                                            // B8

    agg_phase<2>(d_h1, bch, d_g, h_prev, out, N, sCS);
}

// ---------------- launch: ONE kernel ----------------
extern "C" void kernel_launch(void* const* d_in, const int* in_sizes, int n_in,
                              void* d_out, int out_size)
{
    const float* x      = (const float*)d_in[0];
    const void*  ei     = d_in[1];
    const float* h_prev = (const float*)d_in[2];
    const float* Wx     = (const float*)d_in[3];
    const float* bx     = (const float*)d_in[4];
    const float* Wuh    = (const float*)d_in[5];
    const float* buh    = (const float*)d_in[6];
    const float* Wch    = (const float*)d_in[7];
    const float* bch    = (const float*)d_in[8];
    float*       out    = (float*)d_out;

    int N = in_sizes[0] / C;
    int E = in_sizes[1] / 2;
    if (N > NMAX) N = NMAX;
    if (E > EMAX) E = EMAX;

    const int SMEM_BYTES = C * C * (int)sizeof(float) + 8 * 32 * (int)sizeof(int2);

    cudaFuncSetAttribute(mega_kernel,
                         cudaFuncAttributeMaxDynamicSharedMemorySize, SMEM_BYTES);

    int dev = 0;
    cudaGetDevice(&dev);
    int nsm = 148;
    cudaDeviceGetAttribute(&nsm, cudaDevAttrMultiProcessorCount, dev);
    int occ = 1;
    cudaOccupancyMaxActiveBlocksPerMultiprocessor(&occ, mega_kernel, 256, SMEM_BYTES);
    if (occ < 1) occ = 1;
    int grid = nsm * occ;   // guaranteed co-resident -> grid barrier is safe

    mega_kernel<<<grid, 256, SMEM_BYTES>>>(
        x, ei, h_prev, Wx, bx, Wuh, buh, Wch, bch, out, N, E);
}

// round 11
// speedup vs baseline: 1.0234x; 1.0234x over previous
#include <cuda_runtime.h>

// ---------------- problem constants ----------------
#define C 96                 // feature channels (d = h = 96)
#define NMAX 65536
#define EMAX 1048576

// ---------------- device scratch (no allocations allowed) ----------------
// NOTE: d_deg relies on static zero-init for the FIRST call; every call
// re-zeroes it during the fill phase for the next graph replay.
__device__ int   d_deg[NMAX];
__device__ int   d_rowptr[NMAX];       // tile-LOCAL exclusive scan
__device__ int   d_cursor[NMAX];       // tile-LOCAL fill cursor (post-fill: local end)
__device__ int   d_bsum[1024];         // per-tile degree totals
__device__ int   d_boff[1024];         // per-tile global offsets
__device__ int2  d_csr[EMAX];
__device__ float d_dinv[NMAX];
__device__ float d_h1[(size_t)NMAX * C];
__device__ float d_xgcn[(size_t)NMAX * C];
__device__ float d_g[(size_t)NMAX * C];

// grid-barrier state (monotonic generation; survives across graph replays)
__device__ unsigned          d_barcnt = 0;
__device__ volatile unsigned d_bargen = 0;
__device__ unsigned          d_p2done = 0;   // last-block ticket for mid-scan

// ---------------- helpers ----------------
__device__ __forceinline__ float fsigmoid(float x) {
    return 1.0f / (1.0f + __expf(-x));
}
__device__ __forceinline__ float ftanh(float x) {
    return 1.0f - 2.0f / (__expf(2.0f * x) + 1.0f);
}
__device__ __forceinline__ int load_idx(const void* ei, int idx, int is64) {
    if (is64) return (int)((const long long*)ei)[idx];
    return ((const int*)ei)[idx];
}

// Software grid barrier (all blocks co-resident; grid sized via occupancy API).
__device__ __forceinline__ void grid_barrier() {
    __threadfence();
    __syncthreads();
    if (threadIdx.x == 0) {
        unsigned g = d_bargen;
        unsigned t = atomicAdd(&d_barcnt, 1u);
        if (t == gridDim.x - 1) {
            atomicExch(&d_barcnt, 0u);
            __threadfence();
            d_bargen = g + 1;
        } else {
            while (d_bargen == g) __nanosleep(64);
        }
    }
    __syncthreads();
    __threadfence();
}

// ---------------- GEMM phase (R9 config: 2 rows/thread, measured best) ----
// out[N,96] = A[N,K] @ W[K,96]; K in 96-row segments, one staged in smem.
// Segment 1 accumulates via out += (same thread owns the same elements).
// Warp owns 8 rows x 96 cols: lane (g=lane&7, s=lane>>3) holds acc[2][12]
// for rows (tile*64 + wid*8 + s*2 +{0,1}), cols g*12..+11.
// Per 8-k chunk: 4 LDG.128 (A), inner 8x(3 LDS.128 W -> 24 FMA).
template <int MODE>
__device__ __forceinline__ void gemm_load_row8(
    const float* __restrict__ Asrc, const float* __restrict__ A2,
    int seg, int row, int k0, bool valid, float4* p)
{
    if (!valid) {
        p[0] = p[1] = make_float4(0.f, 0.f, 0.f, 0.f);
        return;
    }
    const float* b = Asrc + (size_t)row * C + k0;
    p[0] = *(const float4*)(b);
    p[1] = *(const float4*)(b + 4);
    if (MODE == 2 && seg == 1) {
        const float* gb = A2 + (size_t)row * C + k0;
        float4 g0 = *(const float4*)(gb);
        float4 g1 = *(const float4*)(gb + 4);
        p[0].x *= g0.x; p[0].y *= g0.y; p[0].z *= g0.z; p[0].w *= g0.w;
        p[1].x *= g1.x; p[1].y *= g1.y; p[1].z *= g1.z; p[1].w *= g1.w;
    }
}

template <int MODE>
__device__ void gemm_phase(
    const float* __restrict__ A0, const float* __restrict__ A1,
    const float* __restrict__ A2, const float* __restrict__ W,
    float* __restrict__ outp, int N, float* sW)
{
    const int NSEG = (MODE == 0) ? 1 : 2;
    const int tid  = threadIdx.x;
    const int lane = tid & 31;
    const int wid  = tid >> 5;
    const int g    = lane & 7;
    const int s    = lane >> 3;
    const int ntile = (N + 63) / 64;

    for (int seg = 0; seg < NSEG; seg++) {
        __syncthreads();                          // prior users of sW done
        const float* wseg = W + (size_t)seg * C * C;
        for (int i = tid * 4; i < C * C; i += 256 * 4)
            *(float4*)&sW[i] = *(const float4*)&wseg[i];
        __syncthreads();

        const float* Asrc = (seg == 0) ? A0 : A1;

        for (int tile = blockIdx.x; tile < ntile; tile += gridDim.x) {
            const int row0 = tile * 64 + wid * 8 + s * 2;
            const int row1 = row0 + 1;
            const bool v0 = row0 < N;
            const bool v1 = row1 < N;

            float acc0[12], acc1[12];
            #pragma unroll
            for (int c2 = 0; c2 < 12; c2++) { acc0[c2] = 0.0f; acc1[c2] = 0.0f; }

            #pragma unroll 1
            for (int ch = 0; ch < 12; ch++) {     // 8-k chunks
                const int k0 = ch * 8;
                float4 p0[2], p1[2];
                gemm_load_row8<MODE>(Asrc, A2, seg, row0, k0, v0, p0);
                gemm_load_row8<MODE>(Asrc, A2, seg, row1, k0, v1, p1);

                float a0[8], a1[8];
                a0[0]=p0[0].x; a0[1]=p0[0].y; a0[2]=p0[0].z; a0[3]=p0[0].w;
                a0[4]=p0[1].x; a0[5]=p0[1].y; a0[6]=p0[1].z; a0[7]=p0[1].w;
                a1[0]=p1[0].x; a1[1]=p1[0].y; a1[2]=p1[0].z; a1[3]=p1[0].w;
                a1[4]=p1[1].x; a1[5]=p1[1].y; a1[6]=p1[1].z; a1[7]=p1[1].w;

                const float* wbase = &sW[k0 * C + g * 12];
                #pragma unroll
                for (int kk = 0; kk < 8; kk++) {
                    const float* wr = wbase + kk * C;
                    float4 w0 = *(const float4*)(wr);
                    float4 w1 = *(const float4*)(wr + 4);
                    float4 w2 = *(const float4*)(wr + 8);
                    float av0 = a0[kk], av1 = a1[kk];
                    acc0[0]  += av0 * w0.x; acc0[1]  += av0 * w0.y;
                    acc0[2]  += av0 * w0.z; acc0[3]  += av0 * w0.w;
                    acc0[4]  += av0 * w1.x; acc0[5]  += av0 * w1.y;
                    acc0[6]  += av0 * w1.z; acc0[7]  += av0 * w1.w;
                    acc0[8]  += av0 * w2.x; acc0[9]  += av0 * w2.y;
                    acc0[10] += av0 * w2.z; acc0[11] += av0 * w2.w;
                    acc1[0]  += av1 * w0.x; acc1[1]  += av1 * w0.y;
                    acc1[2]  += av1 * w0.z; acc1[3]  += av1 * w0.w;
                    acc1[4]  += av1 * w1.x; acc1[5]  += av1 * w1.y;
                    acc1[6]  += av1 * w1.z; acc1[7]  += av1 * w1.w;
                    acc1[8]  += av1 * w2.x; acc1[9]  += av1 * w2.y;
                    acc1[10] += av1 * w2.z; acc1[11] += av1 * w2.w;
                }
            }

            #pragma unroll
            for (int r = 0; r < 2; r++) {
                const int   row = r ? row1 : row0;
                const float* ac = r ? acc1 : acc0;
                if (row < N) {
                    float* o = outp + (size_t)row * C + g * 12;
                    if (seg == 0) {
                        *(float4*)(o)     = make_float4(ac[0], ac[1], ac[2],  ac[3]);
                        *(float4*)(o + 4) = make_float4(ac[4], ac[5], ac[6],  ac[7]);
                        *(float4*)(o + 8) = make_float4(ac[8], ac[9], ac[10], ac[11]);
                    } else {
                        float4 o0 = *(float4*)(o);
                        float4 o1 = *(float4*)(o + 4);
                        float4 o2 = *(float4*)(o + 8);
                        *(float4*)(o)     = make_float4(o0.x + ac[0], o0.y + ac[1],
                                                        o0.z + ac[2], o0.w + ac[3]);
                        *(float4*)(o + 4) = make_float4(o1.x + ac[4], o1.y + ac[5],
                                                        o1.z + ac[6], o1.w + ac[7]);
                        *(float4*)(o + 8) = make_float4(o2.x + ac[8], o2.y + ac[9],
                                                        o2.z + ac[10], o2.w + ac[11]);
                    }
                }
            }
        }
    }
}

// ---------------- aggregation phase ----------------
// task = (node, channel-third); lane owns channel third*32+lane.
// jbeg = local rowptr + tile offset; jend from post-fill cursor (== rowptr+deg).
template <int MODE>
__device__ void agg_phase(
    const float* __restrict__ H, const float* __restrict__ bias,
    const float* __restrict__ G, const float* __restrict__ HP,
    float* __restrict__ outp, int N, int2* sCS)
{
    const int wid  = threadIdx.x >> 5;
    const int lane = threadIdx.x & 31;
    int2* cs = &sCS[wid * 32];
    const int ntask = 3 * N;

    for (int task = blockIdx.x * 8 + wid; task < ntask; task += gridDim.x * 8) {
        const int n     = task / 3;
        const int third = task - n * 3;
        const int c     = third * 32 + lane;

        float dn = d_dinv[n];
        float a  = bias[c] + dn * dn * H[(size_t)n * C + c];

        const int boff = d_boff[n >> 8];
        const int jbeg = d_rowptr[n] + boff;
        const int jend = d_cursor[n] + boff;

        for (int base = jbeg; base < jend; base += 32) {
            int cnt = jend - base;
            if (cnt > 32) cnt = 32;
            if (lane < cnt) cs[lane] = d_csr[base + lane];
            __syncwarp();
            int t = 0;
            for (; t + 8 <= cnt; t += 8) {
                float xv[8], wv[8];
                #pragma unroll
                for (int q = 0; q < 8; q++) {
                    int2 e = cs[t + q];
                    wv[q] = __int_as_float(e.y);
                    xv[q] = H[(size_t)e.x * C + c];
                }
                #pragma unroll
                for (int q = 0; q < 8; q++) a += wv[q] * xv[q];
            }
            for (; t < cnt; t++) {
                int2 e = cs[t];
                a += __int_as_float(e.y) * H[(size_t)e.x * C + c];
            }
            __syncwarp();
        }

        const size_t o = (size_t)n * C + c;
        if (MODE == 0) {
            outp[o] = a;
        } else if (MODE == 1) {
            outp[o] = fsigmoid(a);
        } else {
            float u = G[o];
            outp[o] = u * HP[o] + (1.0f - u) * ftanh(a);
        }
    }
}

// ---------------- the megakernel (7 grid barriers) ----------------
__global__ void __launch_bounds__(256, 4) mega_kernel(
    const float* __restrict__ x, const void* __restrict__ ei,
    const float* __restrict__ h_prev,
    const float* __restrict__ Wx,  const float* __restrict__ bx,
    const float* __restrict__ Wuh, const float* __restrict__ buh,
    const float* __restrict__ Wch, const float* __restrict__ bch,
    float* __restrict__ out, int N, int E)
{
    extern __shared__ float sW[];                 // [C*C] floats (36 KB)
    int2* sCS = (int2*)(sW + C * C);              // [8*32] int2 (2 KB)
    int*  sSc = (int*)sCS;                        // scan scratch (aliased)
    __shared__ int sIs64;

    const int tid  = threadIdx.x;
    const int NB   = gridDim.x;
    const int gtid = blockIdx.x * 256 + tid;
    const int nthr = NB * 256;
    const int lane = tid & 31;
    const int wid  = tid >> 5;

    // ---- Phase A: block-local dtype detect + histogram + gemm<0> ----
    // detect: int64 values < 2^31 have zero high words at odd int32 slots.
    {
        int lim = 2 * E; if (lim > 8192) lim = 8192;
        int nz = 0;
        const int* e32 = (const int*)ei;
        for (int i = 1 + 2 * tid; i < lim; i += 512) nz |= e32[i];
        #pragma unroll
        for (int off = 16; off > 0; off >>= 1)
            nz |= __shfl_xor_sync(0xffffffffu, nz, off);
        if (lane == 0) sSc[wid] = nz;
        __syncthreads();
        if (tid == 0) {
            int r = 0;
            #pragma unroll
            for (int w = 0; w < 8; w++) r |= sSc[w];
            sIs64 = (r == 0) ? 1 : 0;
        }
        __syncthreads();
    }
    const int is64 = sIs64;

    // histogram (d_deg is zero at entry: static init on call 1, re-zeroed in
    // phase D on every call thereafter)
    for (int e = gtid; e < E; e += nthr) {
        int d = load_idx(ei, E + e, is64);
        if ((unsigned)d < (unsigned)N) atomicAdd(&d_deg[d], 1);
    }
    // gemm<0> (independent of CSR pipeline; overlaps other blocks' hist tail)
    gemm_phase<0>(x, nullptr, nullptr, Wx, d_h1, N, sW);
    grid_barrier();                                            // B1

    // ---- Phase C: per-tile local scan + dinv; LAST block does mid-scan ----
    const int ntiles = (N + 255) / 256;
    for (int tile = blockIdx.x; tile < ntiles; tile += NB) {
        int i = tile * 256 + tid;
        int v = (i < N) ? d_deg[i] : 0;
        if (i < N) d_dinv[i] = rsqrtf((float)v + 1.0f);
        int xv = v;
        #pragma unroll
        for (int off = 1; off < 32; off <<= 1) {
            int y = __shfl_up_sync(0xffffffffu, xv, off);
            if (lane >= off) xv += y;
        }
        if (lane == 31) sSc[wid] = xv;
        __syncthreads();
        if (wid == 0 && lane < 8) {
            int s2 = sSc[lane];
            #pragma unroll
            for (int off = 1; off < 8; off <<= 1) {
                int y = __shfl_up_sync(0xffu, s2, off);
                if (lane >= off) s2 += y;
            }
            sSc[lane] = s2;
        }
        __syncthreads();
        int incl = xv + ((wid > 0) ? sSc[wid - 1] : 0);
        if (i < N) {
            int excl = incl - v;
            d_rowptr[i] = excl;                    // tile-local
            d_cursor[i] = excl;
        }
        if (tid == 255) d_bsum[tile] = incl;
        __syncthreads();
    }
    // last-block ticket -> mid-scan of tile totals
    {
        __shared__ int amLast;
        __threadfence();
        __syncthreads();
        if (tid == 0) {
            unsigned t = atomicAdd(&d_p2done, 1u);
            amLast = (t == (unsigned)(NB - 1));
            if (amLast) d_p2done = 0;
        }
        __syncthreads();
        if (amLast) {
            __threadfence();                       // acquire bsum writes
            int v = (tid < ntiles) ? d_bsum[tid] : 0;
            int xv = v;
            #pragma unroll
            for (int off = 1; off < 32; off <<= 1) {
                int y = __shfl_up_sync(0xffffffffu, xv, off);
                if (lane >= off) xv += y;
            }
            if (lane == 31) sSc[wid] = xv;
            __syncthreads();
            if (wid == 0 && lane < 8) {
                int s2 = sSc[lane];
                #pragma unroll
                for (int off = 1; off < 8; off <<= 1) {
                    int y = __shfl_up_sync(0xffu, s2, off);
                    if (lane >= off) s2 += y;
                }
                sSc[lane] = s2;
            }
            __syncthreads();
            int incl = xv + ((wid > 0) ? sSc[wid - 1] : 0);
            if (tid < ntiles) d_boff[tid] = incl - v;
        }
    }
    grid_barrier();                                            // B2

    // ---- Phase D: CSR fill + re-zero d_deg for the next call ----
    // (d_deg is dead after phase C; agg takes extents from d_cursor.)
    for (int e = gtid; e < E; e += nthr) {
        int s = load_idx(ei, e, is64);
        int d = load_idx(ei, E + e, is64);
        if ((unsigned)s < (unsigned)N && (unsigned)d < (unsigned)N) {
            int p = atomicAdd(&d_cursor[d], 1) + d_boff[d >> 8];
            d_csr[p] = make_int2(s, __float_as_int(d_dinv[s] * d_dinv[d]));
        }
    }
    for (int i = gtid; i < N; i += nthr) d_deg[i] = 0;
    grid_barrier();                                            // B3

    // ---- Phases E..I: agg0, gemm1, agg1, gemm2, agg2 ----
    agg_phase<0>(d_h1, bx, nullptr, nullptr, d_xgcn, N, sCS);
    grid_barrier();                                            // B4

    gemm_phase<1>(d_xgcn, h_prev, nullptr, Wuh, d_h1, N, sW);
    grid_barrier();                                            // B5

    agg_phase<1>(d_h1, buh, nullptr, nullptr, d_g, N, sCS);
    grid_barrier();                                            // B6

    gemm_phase<2>(d_xgcn, h_prev, d_g, Wch, d_h1, N, sW);
    grid_barrier();                                            // B7

    agg_phase<2>(d_h1, bch, d_g, h_prev, out, N, sCS);
}

// ---------------- launch: ONE kernel ----------------
extern "C" void kernel_launch(void* const* d_in, const int* in_sizes, int n_in,
                              void* d_out, int out_size)
{
    const float* x      = (const float*)d_in[0];
    const void*  ei     = d_in[1];
    const float* h_prev = (const float*)d_in[2];
    const float* Wx     = (const float*)d_in[3];
    const float* bx     = (const float*)d_in[4];
    const float* Wuh    = (const float*)d_in[5];
    const float* buh    = (const float*)d_in[6];
    const float* Wch    = (const float*)d_in[7];
    const float* bch    = (const float*)d_in[8];
    float*       out    = (float*)d_out;

    int N = in_sizes[0] / C;
    int E = in_sizes[1] / 2;
    if (N > NMAX) N = NMAX;
    if (E > EMAX) E = EMAX;

    const int SMEM_BYTES = C * C * (int)sizeof(float) + 8 * 32 * (int)sizeof(int2);

    cudaFuncSetAttribute(mega_kernel,
                         cudaFuncAttributeMaxDynamicSharedMemorySize, SMEM_BYTES);

    int dev = 0;
    cudaGetDevice(&dev);
    int nsm = 148;
    cudaDeviceGetAttribute(&nsm, cudaDevAttrMultiProcessorCount, dev);
    int occ = 1;
    cudaOccupancyMaxActiveBlocksPerMultiprocessor(&occ, mega_kernel, 256, SMEM_BYTES);
    if (occ < 1) occ = 1;
    int grid = nsm * occ;   // guaranteed co-resident -> grid barrier is safe

    mega_kernel<<<grid, 256, SMEM_BYTES>>>(
        x, ei, h_prev, Wx, bx, Wuh, buh, Wch, bch, out, N, E);
}

// round 12
// speedup vs baseline: 1.2510x; 1.2223x over previous
#include <cuda_runtime.h>
#include <cstdint>

// ---------------- problem constants ----------------
#define C 96                 // feature channels (d = h = 96)
#define NMAX 65536
#define EMAX 1048576
#define WPAD 100             // padded k-stride for transposed W in smem
#define SW_FLOATS (C * WPAD) // 9600 floats = 38.4 KB

// ---------------- device scratch (no allocations allowed) ----------------
// NOTE: d_deg relies on static zero-init for the FIRST call; every call
// re-zeroes it during the fill phase for the next graph replay.
__device__ int   d_deg[NMAX];
__device__ int   d_rowptr[NMAX];       // tile-LOCAL exclusive scan
__device__ int   d_cursor[NMAX];       // tile-LOCAL fill cursor (post-fill: local end)
__device__ int   d_bsum[1024];         // per-tile degree totals
__device__ int   d_boff[1024];         // per-tile global offsets
__device__ int2  d_csr[EMAX];
__device__ float d_dinv[NMAX];
__device__ float d_h1[(size_t)NMAX * C];
__device__ float d_xgcn[(size_t)NMAX * C];
__device__ float d_g[(size_t)NMAX * C];

// grid-barrier state (monotonic generation; survives across graph replays)
__device__ unsigned          d_barcnt = 0;
__device__ volatile unsigned d_bargen = 0;
__device__ unsigned          d_p2done = 0;   // last-block ticket for mid-scan

// ---------------- helpers ----------------
__device__ __forceinline__ float fsigmoid(float x) {
    return 1.0f / (1.0f + __expf(-x));
}
__device__ __forceinline__ float ftanh(float x) {
    return 1.0f - 2.0f / (__expf(2.0f * x) + 1.0f);
}
__device__ __forceinline__ int load_idx(const void* ei, int idx, int is64) {
    if (is64) return (int)((const long long*)ei)[idx];
    return ((const int*)ei)[idx];
}

__device__ __forceinline__ uint32_t f2tf32(float f) {
    uint32_t r;
    asm("cvt.rna.tf32.f32 %0, %1;" : "=r"(r) : "f"(f));
    return r;
}

// D += A(16x8 tf32) * B(8x8 tf32), fp32 accumulate. Row-major A, col-major B.
__device__ __forceinline__ void mma_tf32(
    float* c, uint32_t a0, uint32_t a1, uint32_t a2, uint32_t a3,
    uint32_t b0, uint32_t b1)
{
    asm volatile(
        "mma.sync.aligned.m16n8k8.row.col.f32.tf32.tf32.f32 "
        "{%0,%1,%2,%3}, {%4,%5,%6,%7}, {%8,%9}, {%0,%1,%2,%3};"
        : "+f"(c[0]), "+f"(c[1]), "+f"(c[2]), "+f"(c[3])
        : "r"(a0), "r"(a1), "r"(a2), "r"(a3), "r"(b0), "r"(b1));
}

// Software grid barrier (all blocks co-resident; grid sized via occupancy API).
__device__ __forceinline__ void grid_barrier() {
    __threadfence();
    __syncthreads();
    if (threadIdx.x == 0) {
        unsigned g = d_bargen;
        unsigned t = atomicAdd(&d_barcnt, 1u);
        if (t == gridDim.x - 1) {
            atomicExch(&d_barcnt, 0u);
            __threadfence();
            d_bargen = g + 1;
        } else {
            while (d_bargen == g) __nanosleep(64);
        }
    }
    __syncthreads();
    __threadfence();
}

// ---------------- GEMM phase v6: TF32 mma.sync, A-split compensation ------
// out[N,96] = A[N,K] @ W[K,96]; K in 96-row segments. Per segment, W is
// tf32-rounded ONCE while staging into smem TRANSPOSED with pad stride 100
// (bank map (4n+k)%32: conflict-free B-fragment loads).
// D = A_hi@W' + A_lo@W'  (A_hi = tf32(a), A_lo = tf32(a - A_hi)): x-side
// rounding compensated to ~2^-22; W' perturbation ~1e-4 rel (budget 1e-3).
// Warp task = 16 rows x 48 cols (6 n-tiles): acc[6][4], ~55 regs, occ 4.
// Segment 1 accumulates via out += (same thread owns the same elements).
template <int MODE>
__device__ void gemm_phase(
    const float* __restrict__ A0, const float* __restrict__ A1,
    const float* __restrict__ A2, const float* __restrict__ W,
    float* __restrict__ outp, int N, float* sWt)
{
    const int NSEG = (MODE == 0) ? 1 : 2;
    const int tid  = threadIdx.x;
    const int lane = tid & 31;
    const int wid  = tid >> 5;
    const int gwarp = blockIdx.x * 8 + wid;
    const int nwarp = gridDim.x * 8;
    const int rowtiles = (N + 15) >> 4;
    const int ntask = rowtiles * 2;          // x2 column halves

    const int lg = lane >> 2;                // 0..7
    const int kl = lane & 3;                 // 0..3

    for (int seg = 0; seg < NSEG; seg++) {
        __syncthreads();                      // prior users of sWt done
        const float* wseg = W + (size_t)seg * C * C;
        for (int i = tid; i < C * C; i += 256) {
            int k = i / C, n = i - k * C;     // i = k*96+n (coalesced gmem read)
            sWt[n * WPAD + k] = __uint_as_float(f2tf32(wseg[i]));
        }
        __syncthreads();

        const float* Asrc = (seg == 0) ? A0 : A1;

        for (int task = gwarp; task < ntask; task += nwarp) {
            const int rt   = task >> 1;
            const int half = task & 1;
            const int r0 = rt * 16 + lg;
            const int r1 = r0 + 8;
            const bool v0 = r0 < N;
            const bool v1 = r1 < N;
            const float* __restrict__ arow0 = Asrc + (size_t)r0 * C;
            const float* __restrict__ arow1 = Asrc + (size_t)r1 * C;

            float acc[6][4];
            #pragma unroll
            for (int nt = 0; nt < 6; nt++)
                #pragma unroll
                for (int q = 0; q < 4; q++) acc[nt][q] = 0.0f;

            #pragma unroll 2
            for (int ks = 0; ks < 12; ks++) {
                const int k0 = ks * 8;
                float a0 = v0 ? arow0[k0 + kl]     : 0.0f;
                float a1 = v1 ? arow1[k0 + kl]     : 0.0f;
                float a2 = v0 ? arow0[k0 + 4 + kl] : 0.0f;
                float a3 = v1 ? arow1[k0 + 4 + kl] : 0.0f;
                if (MODE == 2 && seg == 1) {
                    if (v0) {
                        a0 *= A2[(size_t)r0 * C + k0 + kl];
                        a2 *= A2[(size_t)r0 * C + k0 + 4 + kl];
                    }
                    if (v1) {
                        a1 *= A2[(size_t)r1 * C + k0 + kl];
                        a3 *= A2[(size_t)r1 * C + k0 + 4 + kl];
                    }
                }
                // split: hi = tf32(a), lo = tf32(a - hi)
                uint32_t h0 = f2tf32(a0), h1 = f2tf32(a1);
                uint32_t h2 = f2tf32(a2), h3 = f2tf32(a3);
                uint32_t l0 = f2tf32(a0 - __uint_as_float(h0));
                uint32_t l1 = f2tf32(a1 - __uint_as_float(h1));
                uint32_t l2 = f2tf32(a2 - __uint_as_float(h2));
                uint32_t l3 = f2tf32(a3 - __uint_as_float(h3));

                const float* wb = sWt + (size_t)(half * 48 + lg) * WPAD + k0 + kl;
                #pragma unroll
                for (int nt = 0; nt < 6; nt++) {
                    uint32_t b0 = __float_as_uint(wb[(size_t)nt * 8 * WPAD]);
                    uint32_t b1 = __float_as_uint(wb[(size_t)nt * 8 * WPAD + 4]);
                    mma_tf32(acc[nt], h0, h1, h2, h3, b0, b1);
                    mma_tf32(acc[nt], l0, l1, l2, l3, b0, b1);
                }
            }

            // store: d0,d1 -> (r0, cc..cc+1); d2,d3 -> (r1, cc..cc+1)
            const int cc = (lane & 3) * 2;
            #pragma unroll
            for (int nt = 0; nt < 6; nt++) {
                const int n0 = half * 48 + nt * 8 + cc;
                if (v0) {
                    float2* p = (float2*)(outp + (size_t)r0 * C + n0);
                    if (seg == 0) {
                        *p = make_float2(acc[nt][0], acc[nt][1]);
                    } else {
                        float2 o = *p;
                        *p = make_float2(o.x + acc[nt][0], o.y + acc[nt][1]);
                    }
                }
                if (v1) {
                    float2* p = (float2*)(outp + (size_t)r1 * C + n0);
                    if (seg == 0) {
                        *p = make_float2(acc[nt][2], acc[nt][3]);
                    } else {
                        float2 o = *p;
                        *p = make_float2(o.x + acc[nt][2], o.y + acc[nt][3]);
                    }
                }
            }
        }
    }
}

// ---------------- aggregation phase ----------------
// task = (node, channel-third); lane owns channel third*32+lane.
// jbeg = local rowptr + tile offset; jend from post-fill cursor (== rowptr+deg).
template <int MODE>
__device__ void agg_phase(
    const float* __restrict__ H, const float* __restrict__ bias,
    const float* __restrict__ G, const float* __restrict__ HP,
    float* __restrict__ outp, int N, int2* sCS)
{
    const int wid  = threadIdx.x >> 5;
    const int lane = threadIdx.x & 31;
    int2* cs = &sCS[wid * 32];
    const int ntask = 3 * N;

    for (int task = blockIdx.x * 8 + wid; task < ntask; task += gridDim.x * 8) {
        const int n     = task / 3;
        const int third = task - n * 3;
        const int c     = third * 32 + lane;

        float dn = d_dinv[n];
        float a  = bias[c] + dn * dn * H[(size_t)n * C + c];

        const int boff = d_boff[n >> 8];
        const int jbeg = d_rowptr[n] + boff;
        const int jend = d_cursor[n] + boff;

        for (int base = jbeg; base < jend; base += 32) {
            int cnt = jend - base;
            if (cnt > 32) cnt = 32;
            if (lane < cnt) cs[lane] = d_csr[base + lane];
            __syncwarp();
            int t = 0;
            for (; t + 8 <= cnt; t += 8) {
                float xv[8], wv[8];
                #pragma unroll
                for (int q = 0; q < 8; q++) {
                    int2 e = cs[t + q];
                    wv[q] = __int_as_float(e.y);
                    xv[q] = H[(size_t)e.x * C + c];
                }
                #pragma unroll
                for (int q = 0; q < 8; q++) a += wv[q] * xv[q];
            }
            for (; t < cnt; t++) {
                int2 e = cs[t];
                a += __int_as_float(e.y) * H[(size_t)e.x * C + c];
            }
            __syncwarp();
        }

        const size_t o = (size_t)n * C + c;
        if (MODE == 0) {
            outp[o] = a;
        } else if (MODE == 1) {
            outp[o] = fsigmoid(a);
        } else {
            float u = G[o];
            outp[o] = u * HP[o] + (1.0f - u) * ftanh(a);
        }
    }
}

// ---------------- the megakernel (7 grid barriers) ----------------
__global__ void __launch_bounds__(256, 4) mega_kernel(
    const float* __restrict__ x, const void* __restrict__ ei,
    const float* __restrict__ h_prev,
    const float* __restrict__ Wx,  const float* __restrict__ bx,
    const float* __restrict__ Wuh, const float* __restrict__ buh,
    const float* __restrict__ Wch, const float* __restrict__ bch,
    float* __restrict__ out, int N, int E)
{
    extern __shared__ float sWt[];                // [SW_FLOATS] (38.4 KB)
    int2* sCS = (int2*)(sWt + SW_FLOATS);         // [8*32] int2 (2 KB)
    int*  sSc = (int*)sCS;                        // scan scratch (aliased)
    __shared__ int sIs64;

    const int tid  = threadIdx.x;
    const int NB   = gridDim.x;
    const int gtid = blockIdx.x * 256 + tid;
    const int nthr = NB * 256;
    const int lane = tid & 31;
    const int wid  = tid >> 5;

    // ---- Phase A: block-local dtype detect + histogram + gemm<0> ----
    {
        int lim = 2 * E; if (lim > 8192) lim = 8192;
        int nz = 0;
        const int* e32 = (const int*)ei;
        for (int i = 1 + 2 * tid; i < lim; i += 512) nz |= e32[i];
        #pragma unroll
        for (int off = 16; off > 0; off >>= 1)
            nz |= __shfl_xor_sync(0xffffffffu, nz, off);
        if (lane == 0) sSc[wid] = nz;
        __syncthreads();
        if (tid == 0) {
            int r = 0;
            #pragma unroll
            for (int w = 0; w < 8; w++) r |= sSc[w];
            sIs64 = (r == 0) ? 1 : 0;
        }
        __syncthreads();
    }
    const int is64 = sIs64;

    // histogram (d_deg zero at entry: static init call 1, re-zeroed phase D)
    for (int e = gtid; e < E; e += nthr) {
        int d = load_idx(ei, E + e, is64);
        if ((unsigned)d < (unsigned)N) atomicAdd(&d_deg[d], 1);
    }
    // gemm<0> (independent of CSR pipeline)
    gemm_phase<0>(x, nullptr, nullptr, Wx, d_h1, N, sWt);
    grid_barrier();                                            // B1

    // ---- Phase C: per-tile local scan + dinv; LAST block does mid-scan ----
    const int ntiles = (N + 255) / 256;
    for (int tile = blockIdx.x; tile < ntiles; tile += NB) {
        int i = tile * 256 + tid;
        int v = (i < N) ? d_deg[i] : 0;
        if (i < N) d_dinv[i] = rsqrtf((float)v + 1.0f);
        int xv = v;
        #pragma unroll
        for (int off = 1; off < 32; off <<= 1) {
            int y = __shfl_up_sync(0xffffffffu, xv, off);
            if (lane >= off) xv += y;
        }
        if (lane == 31) sSc[wid] = xv;
        __syncthreads();
        if (wid == 0 && lane < 8) {
            int s2 = sSc[lane];
            #pragma unroll
            for (int off = 1; off < 8; off <<= 1) {
                int y = __shfl_up_sync(0xffu, s2, off);
                if (lane >= off) s2 += y;
            }
            sSc[lane] = s2;
        }
        __syncthreads();
        int incl = xv + ((wid > 0) ? sSc[wid - 1] : 0);
        if (i < N) {
            int excl = incl - v;
            d_rowptr[i] = excl;                    // tile-local
            d_cursor[i] = excl;
        }
        if (tid == 255) d_bsum[tile] = incl;
        __syncthreads();
    }
    // last-block ticket -> mid-scan of tile totals
    {
        __shared__ int amLast;
        __threadfence();
        __syncthreads();
        if (tid == 0) {
            unsigned t = atomicAdd(&d_p2done, 1u);
            amLast = (t == (unsigned)(NB - 1));
            if (amLast) d_p2done = 0;
        }
        __syncthreads();
        if (amLast) {
            __threadfence();                       // acquire bsum writes
            int v = (tid < ntiles) ? d_bsum[tid] : 0;
            int xv = v;
            #pragma unroll
            for (int off = 1; off < 32; off <<= 1) {
                int y = __shfl_up_sync(0xffffffffu, xv, off);
                if (lane >= off) xv += y;
            }
            if (lane == 31) sSc[wid] = xv;
            __syncthreads();
            if (wid == 0 && lane < 8) {
                int s2 = sSc[lane];
                #pragma unroll
                for (int off = 1; off < 8; off <<= 1) {
                    int y = __shfl_up_sync(0xffu, s2, off);
                    if (lane >= off) s2 += y;
                }
                sSc[lane] = s2;
            }
            __syncthreads();
            int incl = xv + ((wid > 0) ? sSc[wid - 1] : 0);
            if (tid < ntiles) d_boff[tid] = incl - v;
        }
    }
    grid_barrier();                                            // B2

    // ---- Phase D: CSR fill + re-zero d_deg for the next call ----
    for (int e = gtid; e < E; e += nthr) {
        int s = load_idx(ei, e, is64);
        int d = load_idx(ei, E + e, is64);
        if ((unsigned)s < (unsigned)N && (unsigned)d < (unsigned)N) {
            int p = atomicAdd(&d_cursor[d], 1) + d_boff[d >> 8];
            d_csr[p] = make_int2(s, __float_as_int(d_dinv[s] * d_dinv[d]));
        }
    }
    for (int i = gtid; i < N; i += nthr) d_deg[i] = 0;
    grid_barrier();                                            // B3

    // ---- Phases E..I: agg0, gemm1, agg1, gemm2, agg2 ----
    agg_phase<0>(d_h1, bx, nullptr, nullptr, d_xgcn, N, sCS);
    grid_barrier();                                            // B4

    gemm_phase<1>(d_xgcn, h_prev, nullptr, Wuh, d_h1, N, sWt);
    grid_barrier();                                            // B5

    agg_phase<1>(d_h1, buh, nullptr, nullptr, d_g, N, sCS);
    grid_barrier();                                            // B6

    gemm_phase<2>(d_xgcn, h_prev, d_g, Wch, d_h1, N, sWt);
    grid_barrier();                                            // B7

    agg_phase<2>(d_h1, bch, d_g, h_prev, out, N, sCS);
}

// ---------------- launch: ONE kernel ----------------
extern "C" void kernel_launch(void* const* d_in, const int* in_sizes, int n_in,
                              void* d_out, int out_size)
{
    const float* x      = (const float*)d_in[0];
    const void*  ei     = d_in[1];
    const float* h_prev = (const float*)d_in[2];
    const float* Wx     = (const float*)d_in[3];
    const float* bx     = (const float*)d_in[4];
    const float* Wuh    = (const float*)d_in[5];
    const float* buh    = (const float*)d_in[6];
    const float* Wch    = (const float*)d_in[7];
    const float* bch    = (const float*)d_in[8];
    float*       out    = (float*)d_out;

    int N = in_sizes[0] / C;
    int E = in_sizes[1] / 2;
    if (N > NMAX) N = NMAX;
    if (E > EMAX) E = EMAX;

    const int SMEM_BYTES = SW_FLOATS * (int)sizeof(float) + 8 * 32 * (int)sizeof(int2);

    cudaFuncSetAttribute(mega_kernel,
                         cudaFuncAttributeMaxDynamicSharedMemorySize, SMEM_BYTES);

    int dev = 0;
    cudaGetDevice(&dev);
    int nsm = 148;
    cudaDeviceGetAttribute(&nsm, cudaDevAttrMultiProcessorCount, dev);
    int occ = 1;
    cudaOccupancyMaxActiveBlocksPerMultiprocessor(&occ, mega_kernel, 256, SMEM_BYTES);
    if (occ < 1) occ = 1;
    int grid = nsm * occ;   // guaranteed co-resident -> grid barrier is safe

    mega_kernel<<<grid, 256, SMEM_BYTES>>>(
        x, ei, h_prev, Wx, bx, Wuh, buh, Wch, bch, out, N, E);
}